// round 14
// baseline (speedup 1.0000x reference)
#include <cuda_runtime.h>
#include <cuda_fp16.h>
#include <cstdint>
#include <math.h>

#define B_TOTAL 32768
#define NSLOT   5
#define D_IN    512
#define DK      16
#define NV      7
#define TB      128          // batches per fused block
#define NCHK    (D_IN / 16)  // 32 k-chunks of 16
#define THREADS 256
#define SPS     17           // padded smem-P row stride (floats)

// dynamic smem: sFrag 2048*16B = 32KB ; sP 7*128*17*4 = 60928B  -> 93696B
#define FRAG_U4     2048
#define SMEM_BYTES  (FRAG_U4 * 16 + NV * TB * SPS * 4)

// W fragments in gmem, precomputed by wconv_kernel: [v][(c*2+nt)*32+lane]
__device__ uint4 g_Wfrag[NV][FRAG_U4];

// fp16 2-way split of an fp32 pair, packed: h/l are f16x2 with e0 in low half.
static __device__ __forceinline__ void split2h(float e0, float e1,
                                               uint32_t& h, uint32_t& l) {
    asm("cvt.rn.f16x2.f32 %0, %1, %2;" : "=r"(h) : "f"(e1), "f"(e0));
    __half2 hh = *reinterpret_cast<__half2*>(&h);
    float f0 = __half2float(__low2half(hh));
    float f1 = __half2float(__high2half(hh));
    asm("cvt.rn.f16x2.f32 %0, %1, %2;" : "=r"(l) : "f"(e1 - f1), "f"(e0 - f0));
}

static __device__ __forceinline__ void mma16816h(float* d, const uint32_t* a,
                                                 uint32_t b0, uint32_t b1) {
    asm volatile(
        "mma.sync.aligned.m16n8k16.row.col.f32.f16.f16.f32 "
        "{%0,%1,%2,%3}, {%4,%5,%6,%7}, {%8,%9}, {%0,%1,%2,%3};"
        : "+f"(d[0]), "+f"(d[1]), "+f"(d[2]), "+f"(d[3])
        : "r"(a[0]), "r"(a[1]), "r"(a[2]), "r"(a[3]), "r"(b0), "r"(b1));
}

// ---------------------------------------------------------------------------
// Kernel 0: convert W -> fragment order (same mapping as R13 staging).
// grid (7, 8), 256 threads; one fragment item per thread.
// ---------------------------------------------------------------------------
__global__ __launch_bounds__(THREADS) void wconv_kernel(
    const float* __restrict__ wr, const float* __restrict__ ww)
{
    const int v = blockIdx.x;
    const float* W = (v < 2) ? wr + (size_t)v * D_IN * DK
                             : ww + (size_t)(v - 2) * D_IN * DK;
    int s   = blockIdx.y * THREADS + threadIdx.x;   // 0..2047
    int n   = s & 15;
    int grp = s >> 4;                // 0..127
    int c   = grp >> 2;
    int t4f = grp & 3;
    int d0  = c * 16 + 4 * t4f;
    float w0 = W[(d0 + 0) * DK + n];
    float w1 = W[(d0 + 1) * DK + n];
    float w2 = W[(d0 + 2) * DK + n];
    float w3 = W[(d0 + 3) * DK + n];
    uint4 V;
    split2h(w0, w1, V.x, V.z);       // b0 = cols (d0, d0+1)
    split2h(w2, w3, V.y, V.w);       // b1 = cols (d0+2, d0+3)
    int nt = n >> 3;
    int ln = (n & 7) * 4 + t4f;      // fragment lane = g*4 + t4
    g_Wfrag[v][(c * 2 + nt) * 32 + ln] = V;
}

// ---------------------------------------------------------------------------
// PRNG (identical to all passing rounds)
// ---------------------------------------------------------------------------
__device__ __forceinline__ uint32_t rotl32(uint32_t x, int r) {
    return (x << r) | (x >> (32 - r));
}
__device__ __forceinline__ uint32_t threefry_bits(uint32_t key, uint32_t ctr)
{
    const uint32_t ks0 = 0u, ks1 = key, ks2 = 0x1BD11BDAu ^ key;
    uint32_t x0 = ks0;
    uint32_t x1 = ctr + ks1;
#define R4(a,b,cc,d)                                   \
    x0 += x1; x1 = rotl32(x1,(a));  x1 ^= x0;          \
    x0 += x1; x1 = rotl32(x1,(b));  x1 ^= x0;          \
    x0 += x1; x1 = rotl32(x1,(cc)); x1 ^= x0;          \
    x0 += x1; x1 = rotl32(x1,(d));  x1 ^= x0;
    R4(13,15,26,6);   x0 += ks1; x1 += ks2 + 1u;
    R4(17,29,16,24);  x0 += ks2; x1 += ks0 + 2u;
    R4(13,15,26,6);   x0 += ks0; x1 += ks1 + 3u;
    R4(17,29,16,24);  x0 += ks1; x1 += ks2 + 4u;
    R4(13,15,26,6);   x0 += ks2; x1 += ks0 + 5u;
#undef R4
    return x0 ^ x1;
}
__device__ __forceinline__ float gumbel_from_bits(uint32_t bits)
{
    float u = __uint_as_float((bits >> 9) | 0x3f800000u) - 1.0f;
    float val = fmaxf(1e-10f, u * (1.0f - 1e-10f) + 1e-10f);
    return -logf(-logf(val));
}

// ---------------------------------------------------------------------------
// Fused kernel: 7 projections (GEMM core verbatim from R13, 16 rows/warp)
// + scores + gumbel + argmax + one-hot. grid = 256 blocks x 256 threads.
// ---------------------------------------------------------------------------
__global__ __launch_bounds__(THREADS, 2) void fused_kernel(
    const float* __restrict__ q, const float* __restrict__ kk,
    float* __restrict__ out)
{
    extern __shared__ uint32_t sh[];
    uint4* sFrag = (uint4*)sh;                      // [c][nt][lane]
    float* sP    = (float*)(sh + FRAG_U4 * 4);      // [(v*TB+row)*SPS + col]

    const int tid  = threadIdx.x;
    const int lane = tid & 31;
    const int wid  = tid >> 5;
    const int g    = lane >> 2;
    const int t4   = lane & 3;
    const int bbase = blockIdx.x * TB;

    for (int v = 0; v < NV; v++) {
        // (a) load this v's fragment set (L2-resident)
        #pragma unroll
        for (int t = 0; t < FRAG_U4 / THREADS; t++)
            sFrag[tid + t * THREADS] = g_Wfrag[v][tid + t * THREADS];
        __syncthreads();

        // (b) GEMM: warp rows wid*16 + {g, g+8}
        const float* src = (v < 2) ? q : kk;
        const int slot   = (v < 2) ? v : v - 2;
        const float* ap0 = src + (size_t)(bbase + wid * 16 + g) * (NSLOT * D_IN)
                               + (size_t)slot * D_IN + t4 * 4;
        const float* ap1 = ap0 + (size_t)8 * NSLOT * D_IN;

        float acc[2][4];
        #pragma unroll
        for (int nt = 0; nt < 2; nt++)
            #pragma unroll
            for (int jj = 0; jj < 4; jj++) acc[nt][jj] = 0.0f;

        float4 f0 = *(const float4*)ap0;
        float4 f1 = *(const float4*)ap1;
        float4 p0, p1;

        #pragma unroll 2
        for (int c = 0; c < NCHK; c++) {
            if (c + 1 < NCHK) {
                p0 = *(const float4*)(ap0 + (c + 1) * 16);
                p1 = *(const float4*)(ap1 + (c + 1) * 16);
            }
            uint32_t ah[4], al[4];
            split2h(f0.x, f0.y, ah[0], al[0]);   // row g,   half0
            split2h(f1.x, f1.y, ah[1], al[1]);   // row g+8, half0
            split2h(f0.z, f0.w, ah[2], al[2]);   // row g,   half1
            split2h(f1.z, f1.w, ah[3], al[3]);   // row g+8, half1
            #pragma unroll
            for (int nt = 0; nt < 2; nt++) {
                uint4 V = sFrag[(c * 2 + nt) * 32 + lane];
                mma16816h(acc[nt], ah, V.x, V.y);   // hh
                mma16816h(acc[nt], ah, V.z, V.w);   // hl
                mma16816h(acc[nt], al, V.x, V.y);   // lh
            }
            f0 = p0; f1 = p1;
        }

        // (c) scatter accumulators into smem P
        const int row0 = wid * 16 + g;
        #pragma unroll
        for (int nt = 0; nt < 2; nt++) {
            int col = nt * 8 + t4 * 2;
            sP[(v * TB + row0)     * SPS + col]     = acc[nt][0];
            sP[(v * TB + row0)     * SPS + col + 1] = acc[nt][1];
            sP[(v * TB + row0 + 8) * SPS + col]     = acc[nt][2];
            sP[(v * TB + row0 + 8) * SPS + col + 1] = acc[nt][3];
        }
        __syncthreads();   // P stores visible; sFrag safe to overwrite
    }

    // ---- score phase: thread = (batch b, read-slot r) ----
    const int b  = tid >> 1;
    const int r  = tid & 1;
    const int bg = bbase + b;

    float rv[DK];
    #pragma unroll
    for (int k = 0; k < DK; k++) rv[k] = sP[(r * TB + b) * SPS + k];

    float z[NSLOT];
    #pragma unroll
    for (int m = 0; m < NSLOT; m++) {
        const float* wv = &sP[((2 + m) * TB + b) * SPS];
        float s = 0.0f;
        #pragma unroll
        for (int k = 0; k < DK; k++) s = fmaf(rv[k], wv[k], s);
        s *= 0.25f;
        const uint32_t ctr = (uint32_t)(bg * NSLOT + m);
        z[m] = s + gumbel_from_bits(threefry_bits(42u + (uint32_t)r, ctr));
    }

    int a0 = 0; float bv = z[0];
    #pragma unroll
    for (int m = 1; m < NSLOT; m++)
        if (z[m] > bv) { bv = z[m]; a0 = m; }

    float* o = out + (size_t)r * B_TOTAL * NSLOT + (size_t)bg * NSLOT;
    #pragma unroll
    for (int m = 0; m < NSLOT; m++) o[m] = (m == a0) ? 1.0f : 0.0f;
}

// ---------------------------------------------------------------------------
extern "C" void kernel_launch(void* const* d_in, const int* in_sizes, int n_in,
                              void* d_out, int out_size)
{
    const float* q  = (const float*)d_in[0];
    const float* kk = (const float*)d_in[1];
    const float* wr = (const float*)d_in[2];
    const float* ww = (const float*)d_in[3];
    float* out = (float*)d_out;

    cudaFuncSetAttribute(fused_kernel,
                         cudaFuncAttributeMaxDynamicSharedMemorySize, SMEM_BYTES);

    dim3 gw(NV, FRAG_U4 / THREADS);
    wconv_kernel<<<gw, THREADS>>>(wr, ww);

    fused_kernel<<<B_TOTAL / TB, THREADS, SMEM_BYTES>>>(q, kk, out);
}